// round 7
// baseline (speedup 1.0000x reference)
#include <cuda_runtime.h>

// Problem constants (shapes fixed by the dataset)
#define BB    1024
#define SSEQ  2048
#define FFEAT 9
#define NOUT  8
#define LBK   3
#define DD    11
#define UU    256
#define H1N   512
#define TOUTN 2044
#define RR    8
#define NT    512
#define NBLK  128
#define LN_EPS 1e-3f

typedef unsigned long long u64;

// ---- packed fp32x2 helpers --------------------------------------------------
__device__ __forceinline__ u64 pack2(float lo, float hi) {
    u64 r; asm("mov.b64 %0, {%1,%2};" : "=l"(r) : "f"(lo), "f"(hi)); return r;
}
__device__ __forceinline__ void unpack2(u64 v, float& lo, float& hi) {
    asm("mov.b64 {%0,%1}, %2;" : "=f"(lo), "=f"(hi) : "l"(v));
}
__device__ __forceinline__ void fma2(u64& d, u64 a, u64 b) {
    asm("fma.rn.f32x2 %0, %1, %2, %0;" : "+l"(d) : "l"(a), "l"(b));
}
__device__ __forceinline__ u64 add2(u64 a, u64 b) {
    u64 r; asm("add.rn.f32x2 %0, %1, %2;" : "=l"(r) : "l"(a), "l"(b)); return r;
}

// ---- accurate math ----------------------------------------------------------
__device__ __forceinline__ float rcp_acc(float d) {
    float r0; asm("rcp.approx.f32 %0, %1;" : "=f"(r0) : "f"(d));
    float e = fmaf(-d, r0, 1.0f);
    return fmaf(r0, e, r0);
}
__device__ __forceinline__ float rsqrt_acc(float a) {
    float r; asm("rsqrt.approx.f32 %0, %1;" : "=f"(r) : "f"(a));
    float h = 0.5f * a;
    float e = fmaf(-h, r * r, 0.5f);
    return fmaf(r, e, r);
}
__device__ __forceinline__ float tanh_acc(float x) {
    float ax = fabsf(x);
    if (ax < 0.25f) {
        float x2 = x * x;
        float p = fmaf(x2, 2.1869489e-2f, -5.3968254e-2f);
        p = fmaf(x2, p, 1.3333334e-1f);
        p = fmaf(x2, p, -3.3333334e-1f);
        return fmaf(x * x2, p, x);
    }
    if (ax > 9.1f) return copysignf(1.0f, x);
    float t = ax * 2.88539008177793f;
    float n = rintf(t);
    float f = t - n;
    float p = fmaf(f, 1.5252734e-5f, 1.5403530e-4f);
    p = fmaf(f, p, 1.3333558e-3f);
    p = fmaf(f, p, 9.6181292e-3f);
    p = fmaf(f, p, 5.5504109e-2f);
    p = fmaf(f, p, 2.4022651e-1f);
    p = fmaf(f, p, 6.9314718e-1f);
    p = fmaf(f, p, 1.0f);
    float sc = __int_as_float(((int)n + 127) << 23);
    float q = p * sc;
    float r = rcp_acc(q + 1.0f);
    return copysignf(fmaf(-2.0f, r, 1.0f), x);
}

// 16-FFMA2 GEMV body: 4 consecutive output columns x 8 rows, one float4 weight.
#define GBODY(WV, XSTEP) do {                                                   \
    ulonglong2 x01 = xp[0], x23 = xp[1]; xp += (XSTEP);                          \
    u64 W;                                                                       \
    W = pack2((WV).x, (WV).x); fma2(acc[0],x01.x,W); fma2(acc[1],x01.y,W); fma2(acc[2],x23.x,W); fma2(acc[3],x23.y,W);   \
    W = pack2((WV).y, (WV).y); fma2(acc[4],x01.x,W); fma2(acc[5],x01.y,W); fma2(acc[6],x23.x,W); fma2(acc[7],x23.y,W);   \
    W = pack2((WV).z, (WV).z); fma2(acc[8],x01.x,W); fma2(acc[9],x01.y,W); fma2(acc[10],x23.x,W); fma2(acc[11],x23.y,W); \
    W = pack2((WV).w, (WV).w); fma2(acc[12],x01.x,W); fma2(acc[13],x01.y,W); fma2(acc[14],x23.x,W); fma2(acc[15],x23.y,W); \
} while (0)

#define L1BODY(WS) do {                                                          \
    ulonglong2 x01 = xp[0], x23 = xp[1]; xp += 2;                                \
    u64 W = pack2((WS), (WS));                                                   \
    fma2(a0, x01.x, W); fma2(a1, x01.y, W); fma2(a2, x23.x, W); fma2(a3, x23.y, W); \
} while (0)

// Shared memory. h1T padded to 48B/row (conflict-free transposed stores).
// red: split-K partials, 18-u64 groups (16 used + 2 pad) to dodge conflicts.
struct __align__(16) SmemT {
    float4 xT[LBK * DD][2];
    float4 h1T[H1N][3];
    float4 hT[UU][2];
    float4 combT[UU + 1][2];
    u64    red[512 * 18];
    float  hh[RR][UU + 8];
    float  ss[RR][UU + 8];
    float  gg[RR][H1N + 8];
    float  sdw2[H1N][NOUT];     // dec2 weights
    float  sdw1e[H1N];          // dw1 row 256 (ect column), folded into reduction
    float  sb_eb1[H1N];
    float  sb_db1[H1N];
    float  sb_eb2[UU];
    float  sb_ub[UU];
    float  sb_bw[UU];
    float  sb_g2[UU];
    float  sb_be2[UU];
    float  sb_db2[NOUT];
    float  sb_g1[DD];
    float  sb_be1[DD];
    float  redF[NT];
    float  win[RR][LBK][NOUT];
    float  yS[RR][NOUT];
    float  uS[RR][2];
};

__global__ __launch_bounds__(NT, 1)
void dps_kernel(const float* __restrict__ inp,
                const float* __restrict__ g1,  const float* __restrict__ be1,
                const float* __restrict__ ew1, const float* __restrict__ eb1,
                const float* __restrict__ ew2, const float* __restrict__ eb2,
                const float* __restrict__ uw,  const float* __restrict__ ub,
                const float* __restrict__ g2,  const float* __restrict__ be2,
                const float* __restrict__ bw,
                const float* __restrict__ dw1, const float* __restrict__ db1,
                const float* __restrict__ dw2, const float* __restrict__ db2,
                const int* __restrict__ fixp,
                float* __restrict__ out)
{
    extern __shared__ char smraw[];
    SmemT* sm = reinterpret_cast<SmemT*>(smraw);
    const int tid = threadIdx.x;
    const int b0  = blockIdx.x * RR;

    const int f0 = fixp[0];
    const int f1 = fixp[1];

    // ---- one-time init: window, caches -------------------------------------
    for (int idx = tid; idx < RR * LBK * NOUT; idx += NT) {
        int r = idx / (LBK * NOUT);
        int rem = idx % (LBK * NOUT);
        int t = rem / NOUT, c = rem % NOUT;
        sm->win[r][t][c] = inp[(size_t)(b0 + r) * SSEQ * FFEAT + t * FFEAT + 1 + c];
    }
    {
        float* sd = &sm->sdw2[0][0];
        #pragma unroll
        for (int j = 0; j < 8; ++j) sd[j * NT + tid] = dw2[j * NT + tid];
        sm->sb_eb1[tid] = eb1[tid];
        sm->sb_db1[tid] = db1[tid];
        sm->sdw1e[tid]  = dw1[(size_t)UU * H1N + tid];
        if (tid < UU) {
            sm->sb_eb2[tid] = eb2[tid];
            sm->sb_ub[tid]  = ub[tid];
            sm->sb_bw[tid]  = bw[tid];
            sm->sb_g2[tid]  = g2[tid];
            sm->sb_be2[tid] = be2[tid];
        }
        if (tid < NOUT) sm->sb_db2[tid] = db2[tid];
        if (tid < DD) { sm->sb_g1[tid] = g1[tid]; sm->sb_be1[tid] = be1[tid]; }
    }

    float* xTf    = reinterpret_cast<float*>(sm->xT);
    float* combTf = reinterpret_cast<float*>(sm->combT);
    u64*   hTu    = reinterpret_cast<u64*>(sm->hT);

    const int cg6 = tid & 63,  s6 = tid >> 6;   // L2/L3: 64 col-groups x 8 splits
    const int cg7 = tid & 127, s7 = tid >> 7;   // dec1: 128 col-groups x 4 splits

    // ---- phase-0 input prefetch (regs, warps 0-1 only) ----------------------
    float pfL = 0.f, pfLm = 0.f, pfU = 0.f;
    if (tid < RR * LBK) {
        int r = tid / LBK, t = tid % LBK;
        const float* rowp = inp + (size_t)(b0 + r) * SSEQ * FFEAT;
        pfL  = rowp[t * FFEAT];
        pfLm = (t > 0) ? rowp[(t - 1) * FFEAT] : 0.0f;
    } else if (tid >= 32 && tid < 32 + RR * 2) {
        int qq = tid - 32;
        int r = qq >> 1, j = qq & 1;
        int ch = 1 + (j ? f1 : f0);
        pfU = inp[(size_t)(b0 + r) * SSEQ * FFEAT + (size_t)(LBK + 1) * FFEAT + ch];
    }
    __syncthreads();

    for (int i = LBK; i <= SSEQ - 2; ++i) {
        // ---- phase 0 (warps 0-1; bar#1 orders with prev-step dec2-final) ----
        if (tid < 64) asm volatile("bar.sync 1, 64;" ::: "memory");
        if (tid < RR * LBK) {
            int r = tid / LBK, t = tid % LBK;
            float wv[NOUT];
            if (i == LBK) {
                #pragma unroll
                for (int c = 0; c < NOUT; ++c) wv[c] = sm->win[r][t][c];
            } else {
                #pragma unroll
                for (int c = 0; c < NOUT; ++c)
                    wv[c] = (t < LBK - 1) ? sm->win[r][t + 1][c] : sm->yS[r][c];
            }
            __syncwarp(0x00FFFFFFu);
            if (i > LBK) {
                #pragma unroll
                for (int c = 0; c < NOUT; ++c) sm->win[r][t][c] = wv[c];
            }
            int tp = i - LBK + t;
            float L  = pfL;
            float Lm = pfLm;
            float v[DD];
            v[0] = L;
            v[1] = L;                               // cumsum over size-1 axis
            v[2] = (tp > 0) ? (L - Lm) : 0.0f;      // diff padded to 0 at t'=0
            #pragma unroll
            for (int c = 0; c < NOUT; ++c) v[3 + c] = wv[c];
            float s = 0.f;
            #pragma unroll
            for (int j = 0; j < DD; ++j) s += v[j];
            float m = s * (1.0f / DD);
            float q = 0.f;
            #pragma unroll
            for (int j = 0; j < DD; ++j) { float d = v[j] - m; q = fmaf(d, d, q); }
            float invs = rsqrt_acc(q * (1.0f / DD) + LN_EPS);
            #pragma unroll
            for (int j = 0; j < DD; ++j) {
                int k = t * DD + j;
                xTf[k * 8 + r] = fmaf((v[j] - m) * invs, sm->sb_g1[j], sm->sb_be1[j]);
            }
            // prefetch next step's L / Lm
            if (i < SSEQ - 2) {
                const float* rowp = inp + (size_t)(b0 + r) * SSEQ * FFEAT;
                int tp1 = tp + 1;
                pfL  = rowp[tp1 * FFEAT];
                pfLm = rowp[(tp1 - 1) * FFEAT];
            }
        } else if (tid >= 32 && tid < 32 + RR * 2) {
            int qq = tid - 32;
            int r = qq >> 1, j = qq & 1;
            sm->uS[r][j] = pfU;
            if (i < SSEQ - 2) {
                int ch = 1 + (j ? f1 : f0);
                pfU = inp[(size_t)(b0 + r) * SSEQ * FFEAT + (size_t)(i + 2) * FFEAT + ch];
            }
        }
        __syncthreads();   // S2: xT ready

        // ---- L1: h1 = tanh(x33 @ ew1 + eb1)  K=33, N=512 ----
        {
            const int n = tid;
            u64 a0 = 0, a1 = 0, a2 = 0, a3 = 0;
            const float* wp1 = ew1 + n;
            float wa = wp1[0], wb = wp1[H1N], wc = wp1[2 * H1N];
            wp1 += 3 * H1N;
            const ulonglong2* xp = reinterpret_cast<const ulonglong2*>(&sm->xT[0][0]);
            #pragma unroll 3
            for (int k = 0; k < LBK * DD - 3; ++k) {
                float wn = *wp1; wp1 += H1N;
                L1BODY(wa);
                wa = wb; wb = wc; wc = wn;
            }
            L1BODY(wa); L1BODY(wb); L1BODY(wc);
            float v[8];
            unpack2(a0, v[0], v[1]); unpack2(a1, v[2], v[3]);
            unpack2(a2, v[4], v[5]); unpack2(a3, v[6], v[7]);
            float b = sm->sb_eb1[n];
            float4 o0, o1;
            o0.x = tanh_acc(v[0] + b); o0.y = tanh_acc(v[1] + b);
            o0.z = tanh_acc(v[2] + b); o0.w = tanh_acc(v[3] + b);
            o1.x = tanh_acc(v[4] + b); o1.y = tanh_acc(v[5] + b);
            o1.z = tanh_acc(v[6] + b); o1.w = tanh_acc(v[7] + b);
            sm->h1T[n][0] = o0; sm->h1T[n][1] = o1;
        }
        __syncthreads();   // S3: h1T ready

        // ---- L2 main: h1 @ ew2, K=512 (8 splits), 4 consecutive cols/thread
        {
            u64 acc[16];
            #pragma unroll
            for (int j = 0; j < 16; ++j) acc[j] = 0;
            const float4* wp = (const float4*)ew2 + (size_t)(s6 << 6) * 64 + cg6;
            const ulonglong2* xp = reinterpret_cast<const ulonglong2*>(&sm->h1T[s6 << 6][0]);
            float4 wa = wp[0], wb = wp[64], wc = wp[128];
            wp += 192;
            #pragma unroll 3
            for (int kk = 0; kk < 61; ++kk) {
                float4 wn = wp[0]; wp += 64;
                GBODY(wa, 3);
                wa = wb; wb = wc; wc = wn;
            }
            GBODY(wa, 3); GBODY(wb, 3); GBODY(wc, 3);
            ulonglong2* rb = reinterpret_cast<ulonglong2*>(sm->red + ((s6 << 6) + cg6) * 18);
            #pragma unroll
            for (int j = 0; j < 8; ++j) rb[j] = make_ulonglong2(acc[2 * j], acc[2 * j + 1]);
        }
        __syncthreads();   // S4

        // ---- L2 reduction: bias, write hT + hh ----
        {
            #pragma unroll
            for (int rep = 0; rep < 2; ++rep) {
                int o = tid + (rep << 9);
                int cgo = o >> 4, idx = o & 15;
                const u64* rp = sm->red + cgo * 18 + idx;
                u64 a = rp[0];
                #pragma unroll
                for (int sI = 1; sI < 8; ++sI) a = add2(a, rp[sI * 1152]);
                int c = idx >> 2, q = idx & 3;
                int n = (cgo << 2) + c;
                float lo, hi; unpack2(a, lo, hi);
                float b = sm->sb_eb2[n]; lo += b; hi += b;
                hTu[(n << 2) + q] = pack2(lo, hi);
                sm->hh[2 * q][n] = lo; sm->hh[2 * q + 1][n] = hi;
            }
        }
        __syncthreads();   // S5

        // ---- L3 main: h @ uw, K=256 (8 splits) ----
        {
            u64 acc[16];
            #pragma unroll
            for (int j = 0; j < 16; ++j) acc[j] = 0;
            const float4* wp = (const float4*)uw + (size_t)(s6 << 5) * 64 + cg6;
            const ulonglong2* xp = reinterpret_cast<const ulonglong2*>(&sm->hT[s6 << 5][0]);
            float4 wa = wp[0], wb = wp[64], wc = wp[128];
            wp += 192;
            #pragma unroll 3
            for (int kk = 0; kk < 29; ++kk) {
                float4 wn = wp[0]; wp += 64;
                GBODY(wa, 2);
                wa = wb; wb = wc; wc = wn;
            }
            GBODY(wa, 2); GBODY(wb, 2); GBODY(wc, 2);
            ulonglong2* rb = reinterpret_cast<ulonglong2*>(sm->red + ((s6 << 6) + cg6) * 18);
            #pragma unroll
            for (int j = 0; j < 8; ++j) rb[j] = make_ulonglong2(acc[2 * j], acc[2 * j + 1]);
        }
        __syncthreads();   // S6

        // ---- L3 reduction: bias, write ss ----
        {
            #pragma unroll
            for (int rep = 0; rep < 2; ++rep) {
                int o = tid + (rep << 9);
                int cgo = o >> 4, idx = o & 15;
                const u64* rp = sm->red + cgo * 18 + idx;
                u64 a = rp[0];
                #pragma unroll
                for (int sI = 1; sI < 8; ++sI) a = add2(a, rp[sI * 1152]);
                int c = idx >> 2, q = idx & 3;
                int n = (cgo << 2) + c;
                float lo, hi; unpack2(a, lo, hi);
                float b = sm->sb_ub[n]; lo += b; hi += b;
                sm->ss[2 * q][n] = lo; sm->ss[2 * q + 1][n] = hi;
            }
        }
        __syncthreads();   // S7

        // ---- LN2 + ect -> combT ----
        if (tid < 256) {
            int r = tid >> 5, lane = tid & 31;
            float s = 0.f, e = 0.f;
            float vv[8];
            #pragma unroll
            for (int j = 0; j < 8; ++j) {
                int n = lane + (j << 5);
                float v = sm->ss[r][n];
                vv[j] = v;
                s += v;
                e = fmaf(sm->hh[r][n], sm->sb_bw[n], e);
            }
            #pragma unroll
            for (int o = 16; o > 0; o >>= 1) {
                s += __shfl_xor_sync(0xffffffffu, s, o);
                e += __shfl_xor_sync(0xffffffffu, e, o);
            }
            float m = s * (1.0f / UU);
            float q = 0.f;
            #pragma unroll
            for (int j = 0; j < 8; ++j) { float d = vv[j] - m; q = fmaf(d, d, q); }
            #pragma unroll
            for (int o = 16; o > 0; o >>= 1)
                q += __shfl_xor_sync(0xffffffffu, q, o);
            float invs = rsqrt_acc(q * (1.0f / UU) + LN_EPS);
            #pragma unroll
            for (int j = 0; j < 8; ++j) {
                int n = lane + (j << 5);
                combTf[n * 8 + r] = fmaf((vv[j] - m) * invs, sm->sb_g2[n], sm->sb_be2[n]);
            }
            if (lane == 0) combTf[UU * 8 + r] = e;
        }
        __syncthreads();   // S8

        // ---- dec1 main: comb[0:256] @ dw1, K=256 (4 splits, balanced) ----
        {
            u64 acc[16];
            #pragma unroll
            for (int j = 0; j < 16; ++j) acc[j] = 0;
            const float4* wp = (const float4*)dw1 + (size_t)(s7 << 6) * 128 + cg7;
            const ulonglong2* xp = reinterpret_cast<const ulonglong2*>(&sm->combT[s7 << 6][0]);
            float4 wa = wp[0], wb = wp[128], wc = wp[256];
            wp += 384;
            #pragma unroll 3
            for (int kk = 0; kk < 61; ++kk) {
                float4 wn = wp[0]; wp += 128;
                GBODY(wa, 2);
                wa = wb; wb = wc; wc = wn;
            }
            GBODY(wa, 2); GBODY(wb, 2); GBODY(wc, 2);
            ulonglong2* rb = reinterpret_cast<ulonglong2*>(sm->red + ((s7 << 7) + cg7) * 18);
            #pragma unroll
            for (int j = 0; j < 8; ++j) rb[j] = make_ulonglong2(acc[2 * j], acc[2 * j + 1]);
        }
        __syncthreads();   // S9

        // ---- dec1 reduction + ect column + bias + tanh -> gg ----
        {
            #pragma unroll
            for (int rep = 0; rep < 4; ++rep) {
                int o = tid + (rep << 9);
                int cgo = o >> 4, idx = o & 15;
                const u64* rp = sm->red + cgo * 18 + idx;
                u64 a = rp[0];
                #pragma unroll
                for (int sI = 1; sI < 4; ++sI) a = add2(a, rp[sI * 2304]);
                int c = idx >> 2, q = idx & 3;
                int n = (cgo << 2) + c;
                float lo, hi; unpack2(a, lo, hi);
                float b  = sm->sb_db1[n];
                float we = sm->sdw1e[n];
                float elo = combTf[UU * 8 + 2 * q];
                float ehi = combTf[UU * 8 + 2 * q + 1];
                lo = fmaf(elo, we, lo) + b;
                hi = fmaf(ehi, we, hi) + b;
                sm->gg[2 * q][n]     = tanh_acc(lo);
                sm->gg[2 * q + 1][n] = tanh_acc(hi);
            }
        }
        __syncthreads();   // S10

        // ---- dec2 partial: gg @ dw2, K=512 split 8, N=8 ----
        {
            int kg  = tid >> 6;
            int idx = tid & 63;
            int n   = idx & 7;
            int r   = idx >> 3;
            float acc = 0.f;
            int kbase = kg << 6;
            #pragma unroll 8
            for (int kk = 0; kk < 64; ++kk) {
                int k = kbase + kk;
                acc = fmaf(sm->gg[r][k], sm->sdw2[k][n], acc);
            }
            sm->redF[tid] = acc;
        }
        __syncthreads();   // S11

        // ---- dec2 final + output (warps 0,1) ----
        if (tid < 64) {
            int n = tid & 7, r = tid >> 3;
            float y = sm->sb_db2[n];
            #pragma unroll
            for (int j = 0; j < 8; ++j) y += sm->redF[(j << 6) + tid];
            if (n == f0) y = sm->uS[r][0];
            if (n == f1) y = sm->uS[r][1];
            sm->yS[r][n] = y;
            out[(size_t)n * BB * TOUTN + (size_t)(b0 + r) * TOUTN + (i - LBK)] = y;
        }
    }
}

extern "C" void kernel_launch(void* const* d_in, const int* in_sizes, int n_in,
                              void* d_out, int out_size) {
    const float* inp = (const float*)d_in[0];
    const float* g1  = (const float*)d_in[1];
    const float* be1 = (const float*)d_in[2];
    const float* ew1 = (const float*)d_in[3];
    const float* eb1 = (const float*)d_in[4];
    const float* ew2 = (const float*)d_in[5];
    const float* eb2 = (const float*)d_in[6];
    const float* uw  = (const float*)d_in[7];
    const float* ub  = (const float*)d_in[8];
    const float* g2  = (const float*)d_in[9];
    const float* be2 = (const float*)d_in[10];
    const float* bw  = (const float*)d_in[11];
    const float* dw1 = (const float*)d_in[12];
    const float* db1 = (const float*)d_in[13];
    const float* dw2 = (const float*)d_in[14];
    const float* db2 = (const float*)d_in[15];
    const int*  fixp = (const int*)d_in[16];
    float* out = (float*)d_out;

    cudaFuncSetAttribute(dps_kernel, cudaFuncAttributeMaxDynamicSharedMemorySize,
                         (int)sizeof(SmemT));
    dps_kernel<<<NBLK, NT, sizeof(SmemT)>>>(inp, g1, be1, ew1, eb1, ew2, eb2,
                                            uw, ub, g2, be2, bw, dw1, db1,
                                            dw2, db2, fixp, out);
}

// round 13
// speedup vs baseline: 1.6663x; 1.6663x over previous
#include <cuda_runtime.h>

// Problem constants (shapes fixed by the dataset)
#define BB    1024
#define SSEQ  2048
#define FFEAT 9
#define NOUT  8
#define LBK   3
#define DD    11
#define UU    256
#define H1N   512
#define TOUTN 2044
#define RR    8
#define NT    512
#define NBLK  128
#define LN_EPS 1e-3f

typedef unsigned long long u64;

// ---- packed fp32x2 helpers --------------------------------------------------
__device__ __forceinline__ u64 pack2(float lo, float hi) {
    u64 r; asm("mov.b64 %0, {%1,%2};" : "=l"(r) : "f"(lo), "f"(hi)); return r;
}
__device__ __forceinline__ void unpack2(u64 v, float& lo, float& hi) {
    asm("mov.b64 {%0,%1}, %2;" : "=f"(lo), "=f"(hi) : "l"(v));
}
__device__ __forceinline__ void fma2(u64& d, u64 a, u64 b) {
    asm("fma.rn.f32x2 %0, %1, %2, %0;" : "+l"(d) : "l"(a), "l"(b));
}
__device__ __forceinline__ u64 add2(u64 a, u64 b) {
    u64 r; asm("add.rn.f32x2 %0, %1, %2;" : "=l"(r) : "l"(a), "l"(b)); return r;
}

// ---- accurate math ----------------------------------------------------------
__device__ __forceinline__ float rcp_acc(float d) {
    float r0; asm("rcp.approx.f32 %0, %1;" : "=f"(r0) : "f"(d));
    float e = fmaf(-d, r0, 1.0f);
    return fmaf(r0, e, r0);
}
__device__ __forceinline__ float rsqrt_acc(float a) {
    float r; asm("rsqrt.approx.f32 %0, %1;" : "=f"(r) : "f"(a));
    float h = 0.5f * a;
    float e = fmaf(-h, r * r, 0.5f);
    return fmaf(r, e, r);
}
__device__ __forceinline__ float tanh_acc(float x) {
    float ax = fabsf(x);
    if (ax < 0.25f) {
        float x2 = x * x;
        float p = fmaf(x2, 2.1869489e-2f, -5.3968254e-2f);
        p = fmaf(x2, p, 1.3333334e-1f);
        p = fmaf(x2, p, -3.3333334e-1f);
        return fmaf(x * x2, p, x);
    }
    if (ax > 9.1f) return copysignf(1.0f, x);
    float t = ax * 2.88539008177793f;
    float n = rintf(t);
    float f = t - n;
    float p = fmaf(f, 1.5252734e-5f, 1.5403530e-4f);
    p = fmaf(f, p, 1.3333558e-3f);
    p = fmaf(f, p, 9.6181292e-3f);
    p = fmaf(f, p, 5.5504109e-2f);
    p = fmaf(f, p, 2.4022651e-1f);
    p = fmaf(f, p, 6.9314718e-1f);
    p = fmaf(f, p, 1.0f);
    float sc = __int_as_float(((int)n + 127) << 23);
    float q = p * sc;
    float r = rcp_acc(q + 1.0f);
    return copysignf(fmaf(-2.0f, r, 1.0f), x);
}

// Shared memory. h1T padded to 48B/row (conflict-free transposed stores).
// red: split-K partials, 18-u64 groups (16 used + 2 pad) to dodge conflicts.
struct __align__(16) SmemT {
    float4 xT[LBK * DD][2];
    float4 h1T[H1N][3];
    float4 hT[UU][2];
    float4 combT[UU + 1][2];
    u64    red[512 * 18];
    float  hh[RR][UU + 8];
    float  ss[RR][UU + 8];
    float  gg[RR][H1N + 8];
    float  sdw2[H1N][NOUT];     // dec2 weights
    float  sdw1e[H1N];          // dw1 row 256 (ect column), folded into reduction
    float  sb_eb1[H1N];
    float  sb_db1[H1N];
    float  sb_eb2[UU];
    float  sb_ub[UU];
    float  sb_bw[UU];
    float  sb_g2[UU];
    float  sb_be2[UU];
    float  sb_db2[NOUT];
    float  sb_g1[DD];
    float  sb_be1[DD];
    float  redF[NT];
    float  win[RR][LBK][NOUT];
    float  yS[RR][NOUT];
    float  uS[RR][2];
};

__global__ __launch_bounds__(NT, 1)
void dps_kernel(const float* __restrict__ inp,
                const float* __restrict__ g1,  const float* __restrict__ be1,
                const float* __restrict__ ew1, const float* __restrict__ eb1,
                const float* __restrict__ ew2, const float* __restrict__ eb2,
                const float* __restrict__ uw,  const float* __restrict__ ub,
                const float* __restrict__ g2,  const float* __restrict__ be2,
                const float* __restrict__ bw,
                const float* __restrict__ dw1, const float* __restrict__ db1,
                const float* __restrict__ dw2, const float* __restrict__ db2,
                const int* __restrict__ fixp,
                float* __restrict__ out)
{
    extern __shared__ char smraw[];
    SmemT* sm = reinterpret_cast<SmemT*>(smraw);
    const int tid = threadIdx.x;
    const int b0  = blockIdx.x * RR;

    const int f0 = fixp[0];
    const int f1 = fixp[1];

    // ---- one-time init: window + caches ------------------------------------
    for (int idx = tid; idx < RR * LBK * NOUT; idx += NT) {
        int r = idx / (LBK * NOUT);
        int rem = idx % (LBK * NOUT);
        int t = rem / NOUT, c = rem % NOUT;
        sm->win[r][t][c] = inp[(size_t)(b0 + r) * SSEQ * FFEAT + t * FFEAT + 1 + c];
    }
    {
        float* sd = &sm->sdw2[0][0];
        #pragma unroll
        for (int j = 0; j < 8; ++j) sd[j * NT + tid] = dw2[j * NT + tid];
        sm->sb_eb1[tid] = eb1[tid];
        sm->sb_db1[tid] = db1[tid];
        sm->sdw1e[tid]  = dw1[(size_t)UU * H1N + tid];
        if (tid < UU) {
            sm->sb_eb2[tid] = eb2[tid];
            sm->sb_ub[tid]  = ub[tid];
            sm->sb_bw[tid]  = bw[tid];
            sm->sb_g2[tid]  = g2[tid];
            sm->sb_be2[tid] = be2[tid];
        }
        if (tid < NOUT) sm->sb_db2[tid] = db2[tid];
        if (tid < DD) { sm->sb_g1[tid] = g1[tid]; sm->sb_be1[tid] = be1[tid]; }
    }

    float* xTf    = reinterpret_cast<float*>(sm->xT);
    float* combTf = reinterpret_cast<float*>(sm->combT);
    u64*   hTu    = reinterpret_cast<u64*>(sm->hT);

    // thread->tile mappings
    const int cg6 = tid & 63,  s6 = tid >> 6;   // L2/L3: 64 col-groups x 8 splits
    const int cg7 = tid & 127, s7 = tid >> 7;   // dec1: 128 col-groups x 4 splits

    // Step-invariant first-iteration weights, register-resident for the whole
    // kernel: kills the phase-start LDG latency on every step.
    const float  w1first = __ldg(&ew1[tid]);
    const float4 w2first = __ldg((const float4*)ew2 + (size_t)(s6 << 6) * 64 + cg6);
    const float4 w3first = __ldg((const float4*)uw  + (size_t)(s6 << 5) * 64 + cg6);
    const float4 wdfirst = __ldg((const float4*)dw1 + (size_t)(s7 << 6) * 128 + cg7);

    // ---- phase-0 input prefetch (regs, warps 0-1 only) ----------------------
    float pfL = 0.f, pfLm = 0.f, pfU = 0.f;
    if (tid < RR * LBK) {
        int r = tid / LBK, t = tid % LBK;
        const float* rowp = inp + (size_t)(b0 + r) * SSEQ * FFEAT;
        pfL  = rowp[t * FFEAT];
        pfLm = (t > 0) ? rowp[(t - 1) * FFEAT] : 0.0f;
    } else if (tid >= 32 && tid < 32 + RR * 2) {
        int qq = tid - 32;
        int r = qq >> 1, j = qq & 1;
        int ch = 1 + (j ? f1 : f0);
        pfU = inp[(size_t)(b0 + r) * SSEQ * FFEAT + (size_t)(LBK + 1) * FFEAT + ch];
    }
    __syncthreads();

    for (int i = LBK; i <= SSEQ - 2; ++i) {
        // ---- phase 0 (warps 0-1 only; bar#1 orders with prev dec2-final) ----
        if (tid < 64) asm volatile("bar.sync 1, 64;" ::: "memory");
        if (tid < RR * LBK) {
            int r = tid / LBK, t = tid % LBK;
            float wv[NOUT];
            if (i == LBK) {
                #pragma unroll
                for (int c = 0; c < NOUT; ++c) wv[c] = sm->win[r][t][c];
            } else {
                #pragma unroll
                for (int c = 0; c < NOUT; ++c)
                    wv[c] = (t < LBK - 1) ? sm->win[r][t + 1][c] : sm->yS[r][c];
            }
            __syncwarp(0x00FFFFFFu);
            if (i > LBK) {
                #pragma unroll
                for (int c = 0; c < NOUT; ++c) sm->win[r][t][c] = wv[c];
            }
            int tp = i - LBK + t;
            float L  = pfL;
            float Lm = pfLm;
            float v[DD];
            v[0] = L;
            v[1] = L;                               // cumsum over size-1 axis
            v[2] = (tp > 0) ? (L - Lm) : 0.0f;      // diff padded to 0 at t'=0
            #pragma unroll
            for (int c = 0; c < NOUT; ++c) v[3 + c] = wv[c];
            float s = 0.f;
            #pragma unroll
            for (int j = 0; j < DD; ++j) s += v[j];
            float m = s * (1.0f / DD);
            float q = 0.f;
            #pragma unroll
            for (int j = 0; j < DD; ++j) { float d = v[j] - m; q = fmaf(d, d, q); }
            float invs = rsqrt_acc(q * (1.0f / DD) + LN_EPS);
            #pragma unroll
            for (int j = 0; j < DD; ++j) {
                int k = t * DD + j;
                xTf[k * 8 + r] = fmaf((v[j] - m) * invs, sm->sb_g1[j], sm->sb_be1[j]);
            }
            // prefetch next step's L / Lm
            if (i < SSEQ - 2) {
                const float* rowp = inp + (size_t)(b0 + r) * SSEQ * FFEAT;
                int tp1 = tp + 1;
                pfL  = rowp[tp1 * FFEAT];
                pfLm = rowp[(tp1 - 1) * FFEAT];
            }
        } else if (tid >= 32 && tid < 32 + RR * 2) {
            int qq = tid - 32;
            int r = qq >> 1, j = qq & 1;
            sm->uS[r][j] = pfU;
            if (i < SSEQ - 2) {
                int ch = 1 + (j ? f1 : f0);
                pfU = inp[(size_t)(b0 + r) * SSEQ * FFEAT + (size_t)(i + 2) * FFEAT + ch];
            }
        }
        __syncthreads();   // S2: xT ready

        // ---- L1: h1 = tanh(x33 @ ew1 + eb1)  K=33, N=512 (1 col/thread) ----
        {
            const int n = tid;
            u64 a0 = 0, a1 = 0, a2 = 0, a3 = 0;
            float w = w1first;
            const float* wp1 = ew1 + H1N + n;
            #pragma unroll
            for (int k = 0; k < LBK * DD; ++k) {
                float wn = 0.0f;
                if (k < LBK * DD - 1) { wn = *wp1; wp1 += H1N; }
                u64 ww = pack2(w, w);
                ulonglong2 x01 = *reinterpret_cast<const ulonglong2*>(&sm->xT[k][0]);
                ulonglong2 x23 = *reinterpret_cast<const ulonglong2*>(&sm->xT[k][1]);
                fma2(a0, x01.x, ww); fma2(a1, x01.y, ww);
                fma2(a2, x23.x, ww); fma2(a3, x23.y, ww);
                w = wn;
            }
            float v[8];
            unpack2(a0, v[0], v[1]); unpack2(a1, v[2], v[3]);
            unpack2(a2, v[4], v[5]); unpack2(a3, v[6], v[7]);
            float b = sm->sb_eb1[n];
            float4 o0, o1;
            o0.x = tanh_acc(v[0] + b); o0.y = tanh_acc(v[1] + b);
            o0.z = tanh_acc(v[2] + b); o0.w = tanh_acc(v[3] + b);
            o1.x = tanh_acc(v[4] + b); o1.y = tanh_acc(v[5] + b);
            o1.z = tanh_acc(v[6] + b); o1.w = tanh_acc(v[7] + b);
            sm->h1T[n][0] = o0; sm->h1T[n][1] = o1;
        }
        __syncthreads();   // S3: h1T ready

        // ---- L2 main: h1 @ ew2, K=512 (8 splits), 4 consecutive cols/thread
        {
            u64 acc[16];
            #pragma unroll
            for (int j = 0; j < 16; ++j) acc[j] = 0;
            const float4* wp = (const float4*)ew2 + (size_t)((s6 << 6) + 1) * 64 + cg6;
            const ulonglong2* xp = reinterpret_cast<const ulonglong2*>(&sm->h1T[s6 << 6][0]);
            float4 w = w2first;
            #pragma unroll 3
            for (int kk = 0; kk < 63; ++kk) {
                float4 wn = *wp; wp += 64;
                ulonglong2 x01 = xp[0], x23 = xp[1]; xp += 3;
                u64 W;
                W = pack2(w.x, w.x); fma2(acc[0], x01.x, W); fma2(acc[1], x01.y, W); fma2(acc[2], x23.x, W); fma2(acc[3], x23.y, W);
                W = pack2(w.y, w.y); fma2(acc[4], x01.x, W); fma2(acc[5], x01.y, W); fma2(acc[6], x23.x, W); fma2(acc[7], x23.y, W);
                W = pack2(w.z, w.z); fma2(acc[8], x01.x, W); fma2(acc[9], x01.y, W); fma2(acc[10], x23.x, W); fma2(acc[11], x23.y, W);
                W = pack2(w.w, w.w); fma2(acc[12], x01.x, W); fma2(acc[13], x01.y, W); fma2(acc[14], x23.x, W); fma2(acc[15], x23.y, W);
                w = wn;
            }
            {   // final k
                ulonglong2 x01 = xp[0], x23 = xp[1];
                u64 W;
                W = pack2(w.x, w.x); fma2(acc[0], x01.x, W); fma2(acc[1], x01.y, W); fma2(acc[2], x23.x, W); fma2(acc[3], x23.y, W);
                W = pack2(w.y, w.y); fma2(acc[4], x01.x, W); fma2(acc[5], x01.y, W); fma2(acc[6], x23.x, W); fma2(acc[7], x23.y, W);
                W = pack2(w.z, w.z); fma2(acc[8], x01.x, W); fma2(acc[9], x01.y, W); fma2(acc[10], x23.x, W); fma2(acc[11], x23.y, W);
                W = pack2(w.w, w.w); fma2(acc[12], x01.x, W); fma2(acc[13], x01.y, W); fma2(acc[14], x23.x, W); fma2(acc[15], x23.y, W);
            }
            ulonglong2* rb = reinterpret_cast<ulonglong2*>(sm->red + ((s6 << 6) + cg6) * 18);
            #pragma unroll
            for (int j = 0; j < 8; ++j) rb[j] = make_ulonglong2(acc[2 * j], acc[2 * j + 1]);
        }
        __syncthreads();   // S4: partials stored

        // ---- L2 reduction (all 512 threads): bias, write hT + hh ----
        {
            #pragma unroll
            for (int rep = 0; rep < 2; ++rep) {
                int o = tid + (rep << 9);
                int cgo = o >> 4, idx = o & 15;
                const u64* rp = sm->red + cgo * 18 + idx;
                u64 a = rp[0];
                #pragma unroll
                for (int sI = 1; sI < 8; ++sI) a = add2(a, rp[sI * 1152]);
                int c = idx >> 2, q = idx & 3;
                int n = (cgo << 2) + c;
                float lo, hi; unpack2(a, lo, hi);
                float b = sm->sb_eb2[n]; lo += b; hi += b;
                hTu[(n << 2) + q] = pack2(lo, hi);
                sm->hh[2 * q][n] = lo; sm->hh[2 * q + 1][n] = hi;
            }
        }
        __syncthreads();   // S5: hT/hh ready, red free

        // ---- L3 main: h @ uw, K=256 (8 splits) ----
        {
            u64 acc[16];
            #pragma unroll
            for (int j = 0; j < 16; ++j) acc[j] = 0;
            const float4* wp = (const float4*)uw + (size_t)((s6 << 5) + 1) * 64 + cg6;
            const ulonglong2* xp = reinterpret_cast<const ulonglong2*>(&sm->hT[s6 << 5][0]);
            float4 w = w3first;
            #pragma unroll 3
            for (int kk = 0; kk < 31; ++kk) {
                float4 wn = *wp; wp += 64;
                ulonglong2 x01 = xp[0], x23 = xp[1]; xp += 2;
                u64 W;
                W = pack2(w.x, w.x); fma2(acc[0], x01.x, W); fma2(acc[1], x01.y, W); fma2(acc[2], x23.x, W); fma2(acc[3], x23.y, W);
                W = pack2(w.y, w.y); fma2(acc[4], x01.x, W); fma2(acc[5], x01.y, W); fma2(acc[6], x23.x, W); fma2(acc[7], x23.y, W);
                W = pack2(w.z, w.z); fma2(acc[8], x01.x, W); fma2(acc[9], x01.y, W); fma2(acc[10], x23.x, W); fma2(acc[11], x23.y, W);
                W = pack2(w.w, w.w); fma2(acc[12], x01.x, W); fma2(acc[13], x01.y, W); fma2(acc[14], x23.x, W); fma2(acc[15], x23.y, W);
                w = wn;
            }
            {
                ulonglong2 x01 = xp[0], x23 = xp[1];
                u64 W;
                W = pack2(w.x, w.x); fma2(acc[0], x01.x, W); fma2(acc[1], x01.y, W); fma2(acc[2], x23.x, W); fma2(acc[3], x23.y, W);
                W = pack2(w.y, w.y); fma2(acc[4], x01.x, W); fma2(acc[5], x01.y, W); fma2(acc[6], x23.x, W); fma2(acc[7], x23.y, W);
                W = pack2(w.z, w.z); fma2(acc[8], x01.x, W); fma2(acc[9], x01.y, W); fma2(acc[10], x23.x, W); fma2(acc[11], x23.y, W);
                W = pack2(w.w, w.w); fma2(acc[12], x01.x, W); fma2(acc[13], x01.y, W); fma2(acc[14], x23.x, W); fma2(acc[15], x23.y, W);
            }
            ulonglong2* rb = reinterpret_cast<ulonglong2*>(sm->red + ((s6 << 6) + cg6) * 18);
            #pragma unroll
            for (int j = 0; j < 8; ++j) rb[j] = make_ulonglong2(acc[2 * j], acc[2 * j + 1]);
        }
        __syncthreads();   // S6

        // ---- L3 reduction: bias, write ss ----
        {
            #pragma unroll
            for (int rep = 0; rep < 2; ++rep) {
                int o = tid + (rep << 9);
                int cgo = o >> 4, idx = o & 15;
                const u64* rp = sm->red + cgo * 18 + idx;
                u64 a = rp[0];
                #pragma unroll
                for (int sI = 1; sI < 8; ++sI) a = add2(a, rp[sI * 1152]);
                int c = idx >> 2, q = idx & 3;
                int n = (cgo << 2) + c;
                float lo, hi; unpack2(a, lo, hi);
                float b = sm->sb_ub[n]; lo += b; hi += b;
                sm->ss[2 * q][n] = lo; sm->ss[2 * q + 1][n] = hi;
            }
        }
        __syncthreads();   // S7

        // ---- LN2 + ect -> combT (warp w handles row w) ----
        if (tid < 256) {
            int r = tid >> 5, lane = tid & 31;
            float s = 0.f, e = 0.f;
            float vv[8];
            #pragma unroll
            for (int j = 0; j < 8; ++j) {
                int n = lane + (j << 5);
                float v = sm->ss[r][n];
                vv[j] = v;
                s += v;
                e = fmaf(sm->hh[r][n], sm->sb_bw[n], e);
            }
            #pragma unroll
            for (int o = 16; o > 0; o >>= 1) {
                s += __shfl_xor_sync(0xffffffffu, s, o);
                e += __shfl_xor_sync(0xffffffffu, e, o);
            }
            float m = s * (1.0f / UU);
            float q = 0.f;
            #pragma unroll
            for (int j = 0; j < 8; ++j) { float d = vv[j] - m; q = fmaf(d, d, q); }
            #pragma unroll
            for (int o = 16; o > 0; o >>= 1)
                q += __shfl_xor_sync(0xffffffffu, q, o);
            float invs = rsqrt_acc(q * (1.0f / UU) + LN_EPS);
            #pragma unroll
            for (int j = 0; j < 8; ++j) {
                int n = lane + (j << 5);
                combTf[n * 8 + r] = fmaf((vv[j] - m) * invs, sm->sb_g2[n], sm->sb_be2[n]);
            }
            if (lane == 0) combTf[UU * 8 + r] = e;
        }
        __syncthreads();   // S8: combT ready

        // ---- dec1 main: comb[0:256] @ dw1, K=256 (4 splits, balanced) ----
        {
            u64 acc[16];
            #pragma unroll
            for (int j = 0; j < 16; ++j) acc[j] = 0;
            const float4* wp = (const float4*)dw1 + (size_t)((s7 << 6) + 1) * 128 + cg7;
            const ulonglong2* xp = reinterpret_cast<const ulonglong2*>(&sm->combT[s7 << 6][0]);
            float4 w = wdfirst;
            #pragma unroll 3
            for (int kk = 0; kk < 63; ++kk) {
                float4 wn = *wp; wp += 128;
                ulonglong2 x01 = xp[0], x23 = xp[1]; xp += 2;
                u64 W;
                W = pack2(w.x, w.x); fma2(acc[0], x01.x, W); fma2(acc[1], x01.y, W); fma2(acc[2], x23.x, W); fma2(acc[3], x23.y, W);
                W = pack2(w.y, w.y); fma2(acc[4], x01.x, W); fma2(acc[5], x01.y, W); fma2(acc[6], x23.x, W); fma2(acc[7], x23.y, W);
                W = pack2(w.z, w.z); fma2(acc[8], x01.x, W); fma2(acc[9], x01.y, W); fma2(acc[10], x23.x, W); fma2(acc[11], x23.y, W);
                W = pack2(w.w, w.w); fma2(acc[12], x01.x, W); fma2(acc[13], x01.y, W); fma2(acc[14], x23.x, W); fma2(acc[15], x23.y, W);
                w = wn;
            }
            {
                ulonglong2 x01 = xp[0], x23 = xp[1];
                u64 W;
                W = pack2(w.x, w.x); fma2(acc[0], x01.x, W); fma2(acc[1], x01.y, W); fma2(acc[2], x23.x, W); fma2(acc[3], x23.y, W);
                W = pack2(w.y, w.y); fma2(acc[4], x01.x, W); fma2(acc[5], x01.y, W); fma2(acc[6], x23.x, W); fma2(acc[7], x23.y, W);
                W = pack2(w.z, w.z); fma2(acc[8], x01.x, W); fma2(acc[9], x01.y, W); fma2(acc[10], x23.x, W); fma2(acc[11], x23.y, W);
                W = pack2(w.w, w.w); fma2(acc[12], x01.x, W); fma2(acc[13], x01.y, W); fma2(acc[14], x23.x, W); fma2(acc[15], x23.y, W);
            }
            ulonglong2* rb = reinterpret_cast<ulonglong2*>(sm->red + ((s7 << 7) + cg7) * 18);
            #pragma unroll
            for (int j = 0; j < 8; ++j) rb[j] = make_ulonglong2(acc[2 * j], acc[2 * j + 1]);
        }
        __syncthreads();   // S9

        // ---- dec1 reduction + ect column + bias + tanh -> gg ----
        {
            #pragma unroll
            for (int rep = 0; rep < 4; ++rep) {
                int o = tid + (rep << 9);
                int cgo = o >> 4, idx = o & 15;
                const u64* rp = sm->red + cgo * 18 + idx;
                u64 a = rp[0];
                #pragma unroll
                for (int sI = 1; sI < 4; ++sI) a = add2(a, rp[sI * 2304]);
                int c = idx >> 2, q = idx & 3;
                int n = (cgo << 2) + c;
                float lo, hi; unpack2(a, lo, hi);
                float b  = sm->sb_db1[n];
                float we = sm->sdw1e[n];
                float elo = combTf[UU * 8 + 2 * q];
                float ehi = combTf[UU * 8 + 2 * q + 1];
                lo = fmaf(elo, we, lo) + b;
                hi = fmaf(ehi, we, hi) + b;
                sm->gg[2 * q][n]     = tanh_acc(lo);
                sm->gg[2 * q + 1][n] = tanh_acc(hi);
            }
        }
        __syncthreads();   // S10: gg ready

        // ---- dec2 partial: gg @ dw2, K=512 split 8, N=8 ----
        {
            int kg  = tid >> 6;
            int idx = tid & 63;
            int n   = idx & 7;
            int r   = idx >> 3;
            float acc = 0.f;
            int kbase = kg << 6;
            #pragma unroll 8
            for (int kk = 0; kk < 64; ++kk) {
                int k = kbase + kk;
                acc = fmaf(sm->gg[r][k], sm->sdw2[k][n], acc);
            }
            sm->redF[tid] = acc;
        }
        __syncthreads();   // S11

        // ---- dec2 final + output (warps 0,1); loop-top bar#1 orders with phase0
        if (tid < 64) {
            int n = tid & 7, r = tid >> 3;
            float y = sm->sb_db2[n];
            #pragma unroll
            for (int j = 0; j < 8; ++j) y += sm->redF[(j << 6) + tid];
            if (n == f0) y = sm->uS[r][0];
            if (n == f1) y = sm->uS[r][1];
            sm->yS[r][n] = y;
            out[(size_t)n * BB * TOUTN + (size_t)(b0 + r) * TOUTN + (i - LBK)] = y;
        }
    }
}

extern "C" void kernel_launch(void* const* d_in, const int* in_sizes, int n_in,
                              void* d_out, int out_size) {
    const float* inp = (const float*)d_in[0];
    const float* g1  = (const float*)d_in[1];
    const float* be1 = (const float*)d_in[2];
    const float* ew1 = (const float*)d_in[3];
    const float* eb1 = (const float*)d_in[4];
    const float* ew2 = (const float*)d_in[5];
    const float* eb2 = (const float*)d_in[6];
    const float* uw  = (const float*)d_in[7];
    const float* ub  = (const float*)d_in[8];
    const float* g2  = (const float*)d_in[9];
    const float* be2 = (const float*)d_in[10];
    const float* bw  = (const float*)d_in[11];
    const float* dw1 = (const float*)d_in[12];
    const float* db1 = (const float*)d_in[13];
    const float* dw2 = (const float*)d_in[14];
    const float* db2 = (const float*)d_in[15];
    const int*  fixp = (const int*)d_in[16];
    float* out = (float*)d_out;

    cudaFuncSetAttribute(dps_kernel, cudaFuncAttributeMaxDynamicSharedMemorySize,
                         (int)sizeof(SmemT));
    dps_kernel<<<NBLK, NT, sizeof(SmemT)>>>(inp, g1, be1, ew1, eb1, ew2, eb2,
                                            uw, ub, g2, be2, bw, dw1, db1,
                                            dw2, db2, fixp, out);
}

// round 14
// speedup vs baseline: 1.8400x; 1.1042x over previous
#include <cuda_runtime.h>

// Problem constants (shapes fixed by the dataset)
#define BB    1024
#define SSEQ  2048
#define FFEAT 9
#define NOUT  8
#define LBK   3
#define DD    11
#define UU    256
#define H1N   512
#define TOUTN 2044
#define RR    8
#define NT    512
#define NBLK  128
#define LN_EPS 1e-3f

typedef unsigned long long u64;

// ---- packed fp32x2 helpers --------------------------------------------------
__device__ __forceinline__ u64 pack2(float lo, float hi) {
    u64 r; asm("mov.b64 %0, {%1,%2};" : "=l"(r) : "f"(lo), "f"(hi)); return r;
}
__device__ __forceinline__ void unpack2(u64 v, float& lo, float& hi) {
    asm("mov.b64 {%0,%1}, %2;" : "=f"(lo), "=f"(hi) : "l"(v));
}
__device__ __forceinline__ void fma2(u64& d, u64 a, u64 b) {
    asm("fma.rn.f32x2 %0, %1, %2, %0;" : "+l"(d) : "l"(a), "l"(b));
}
__device__ __forceinline__ u64 add2(u64 a, u64 b) {
    u64 r; asm("add.rn.f32x2 %0, %1, %2;" : "=l"(r) : "l"(a), "l"(b)); return r;
}

// ---- accurate math ----------------------------------------------------------
__device__ __forceinline__ float rcp_acc(float d) {
    float r0; asm("rcp.approx.f32 %0, %1;" : "=f"(r0) : "f"(d));
    float e = fmaf(-d, r0, 1.0f);
    return fmaf(r0, e, r0);
}
__device__ __forceinline__ float rsqrt_acc(float a) {
    float r; asm("rsqrt.approx.f32 %0, %1;" : "=f"(r) : "f"(a));
    float h = 0.5f * a;
    float e = fmaf(-h, r * r, 0.5f);
    return fmaf(r, e, r);
}
__device__ __forceinline__ float tanh_acc(float x) {
    float ax = fabsf(x);
    if (ax < 0.25f) {
        float x2 = x * x;
        float p = fmaf(x2, 2.1869489e-2f, -5.3968254e-2f);
        p = fmaf(x2, p, 1.3333334e-1f);
        p = fmaf(x2, p, -3.3333334e-1f);
        return fmaf(x * x2, p, x);
    }
    if (ax > 9.1f) return copysignf(1.0f, x);
    float t = ax * 2.88539008177793f;
    float n = rintf(t);
    float f = t - n;
    float p = fmaf(f, 1.5252734e-5f, 1.5403530e-4f);
    p = fmaf(f, p, 1.3333558e-3f);
    p = fmaf(f, p, 9.6181292e-3f);
    p = fmaf(f, p, 5.5504109e-2f);
    p = fmaf(f, p, 2.4022651e-1f);
    p = fmaf(f, p, 6.9314718e-1f);
    p = fmaf(f, p, 1.0f);
    float sc = __int_as_float(((int)n + 127) << 23);
    float q = p * sc;
    float r = rcp_acc(q + 1.0f);
    return copysignf(fmaf(-2.0f, r, 1.0f), x);
}

// 16-FFMA2 GEMV body with constant-indexed operands (full-unroll friendly).
#define GBODYI(W4, X01, X23) do {                                               \
    u64 W;                                                                       \
    W = pack2((W4).x, (W4).x); fma2(acc[0],(X01).x,W); fma2(acc[1],(X01).y,W); fma2(acc[2],(X23).x,W); fma2(acc[3],(X23).y,W);   \
    W = pack2((W4).y, (W4).y); fma2(acc[4],(X01).x,W); fma2(acc[5],(X01).y,W); fma2(acc[6],(X23).x,W); fma2(acc[7],(X23).y,W);   \
    W = pack2((W4).z, (W4).z); fma2(acc[8],(X01).x,W); fma2(acc[9],(X01).y,W); fma2(acc[10],(X23).x,W); fma2(acc[11],(X23).y,W); \
    W = pack2((W4).w, (W4).w); fma2(acc[12],(X01).x,W); fma2(acc[13],(X01).y,W); fma2(acc[14],(X23).x,W); fma2(acc[15],(X23).y,W); \
} while (0)

// Shared memory. h1T padded to 48B/row (conflict-free transposed stores).
// red: split-K partials, 18-u64 groups (16 used + 2 pad) to dodge conflicts.
struct __align__(16) SmemT {
    float4 xT[LBK * DD][2];
    float4 h1T[H1N][3];
    float4 hT[UU][2];
    float4 combT[UU + 1][2];
    u64    red[512 * 18];
    float  hh[RR][UU + 8];
    float  ss[RR][UU + 8];
    float  gg[RR][H1N + 8];
    float  sdw2[H1N][NOUT];     // dec2 weights
    float  sdw1e[H1N];          // dw1 row 256 (ect column), folded into reduction
    float  sb_eb1[H1N];
    float  sb_db1[H1N];
    float  sb_eb2[UU];
    float  sb_ub[UU];
    float  sb_bw[UU];
    float  sb_g2[UU];
    float  sb_be2[UU];
    float  sb_db2[NOUT];
    float  sb_g1[DD];
    float  sb_be1[DD];
    float  redF[NT];
    float  win[RR][LBK][NOUT];
    float  yS[RR][NOUT];
    float  uS[RR][2];
};

__global__ __launch_bounds__(NT, 1)
void dps_kernel(const float* __restrict__ inp,
                const float* __restrict__ g1,  const float* __restrict__ be1,
                const float* __restrict__ ew1, const float* __restrict__ eb1,
                const float* __restrict__ ew2, const float* __restrict__ eb2,
                const float* __restrict__ uw,  const float* __restrict__ ub,
                const float* __restrict__ g2,  const float* __restrict__ be2,
                const float* __restrict__ bw,
                const float* __restrict__ dw1, const float* __restrict__ db1,
                const float* __restrict__ dw2, const float* __restrict__ db2,
                const int* __restrict__ fixp,
                float* __restrict__ out)
{
    extern __shared__ char smraw[];
    SmemT* sm = reinterpret_cast<SmemT*>(smraw);
    const int tid = threadIdx.x;
    const int b0  = blockIdx.x * RR;

    const int f0 = fixp[0];
    const int f1 = fixp[1];

    // ---- one-time init: window + caches ------------------------------------
    for (int idx = tid; idx < RR * LBK * NOUT; idx += NT) {
        int r = idx / (LBK * NOUT);
        int rem = idx % (LBK * NOUT);
        int t = rem / NOUT, c = rem % NOUT;
        sm->win[r][t][c] = inp[(size_t)(b0 + r) * SSEQ * FFEAT + t * FFEAT + 1 + c];
    }
    {
        float* sd = &sm->sdw2[0][0];
        #pragma unroll
        for (int j = 0; j < 8; ++j) sd[j * NT + tid] = dw2[j * NT + tid];
        sm->sb_eb1[tid] = eb1[tid];
        sm->sb_db1[tid] = db1[tid];
        sm->sdw1e[tid]  = dw1[(size_t)UU * H1N + tid];
        if (tid < UU) {
            sm->sb_eb2[tid] = eb2[tid];
            sm->sb_ub[tid]  = ub[tid];
            sm->sb_bw[tid]  = bw[tid];
            sm->sb_g2[tid]  = g2[tid];
            sm->sb_be2[tid] = be2[tid];
        }
        if (tid < NOUT) sm->sb_db2[tid] = db2[tid];
        if (tid < DD) { sm->sb_g1[tid] = g1[tid]; sm->sb_be1[tid] = be1[tid]; }
    }

    float* xTf    = reinterpret_cast<float*>(sm->xT);
    float* combTf = reinterpret_cast<float*>(sm->combT);
    u64*   hTu    = reinterpret_cast<u64*>(sm->hT);

    // thread->tile mappings
    const int cg6 = tid & 63,  s6 = tid >> 6;   // L2/L3: 64 col-groups x 8 splits
    const int cg7 = tid & 127, s7 = tid >> 7;   // dec1: 128 col-groups x 4 splits

    // ---- phase-0 input prefetch (regs, warps 0-1 only) ----------------------
    float pfL = 0.f, pfLm = 0.f, pfU = 0.f;
    if (tid < RR * LBK) {
        int r = tid / LBK, t = tid % LBK;
        const float* rowp = inp + (size_t)(b0 + r) * SSEQ * FFEAT;
        pfL  = rowp[t * FFEAT];
        pfLm = (t > 0) ? rowp[(t - 1) * FFEAT] : 0.0f;
    } else if (tid >= 32 && tid < 32 + RR * 2) {
        int qq = tid - 32;
        int r = qq >> 1, j = qq & 1;
        int ch = 1 + (j ? f1 : f0);
        pfU = inp[(size_t)(b0 + r) * SSEQ * FFEAT + (size_t)(LBK + 1) * FFEAT + ch];
    }
    __syncthreads();

    for (int i = LBK; i <= SSEQ - 2; ++i) {
        // ---- phase 0 (warps 0-1 only; bar#1 orders with prev dec2-final) ----
        if (tid < 64) asm volatile("bar.sync 1, 64;" ::: "memory");
        if (tid < RR * LBK) {
            int r = tid / LBK, t = tid % LBK;
            float wv[NOUT];
            if (i == LBK) {
                #pragma unroll
                for (int c = 0; c < NOUT; ++c) wv[c] = sm->win[r][t][c];
            } else {
                #pragma unroll
                for (int c = 0; c < NOUT; ++c)
                    wv[c] = (t < LBK - 1) ? sm->win[r][t + 1][c] : sm->yS[r][c];
            }
            __syncwarp(0x00FFFFFFu);
            if (i > LBK) {
                #pragma unroll
                for (int c = 0; c < NOUT; ++c) sm->win[r][t][c] = wv[c];
            }
            int tp = i - LBK + t;
            float L  = pfL;
            float Lm = pfLm;
            float v[DD];
            v[0] = L;
            v[1] = L;                               // cumsum over size-1 axis
            v[2] = (tp > 0) ? (L - Lm) : 0.0f;      // diff padded to 0 at t'=0
            #pragma unroll
            for (int c = 0; c < NOUT; ++c) v[3 + c] = wv[c];
            float s = 0.f;
            #pragma unroll
            for (int j = 0; j < DD; ++j) s += v[j];
            float m = s * (1.0f / DD);
            float q = 0.f;
            #pragma unroll
            for (int j = 0; j < DD; ++j) { float d = v[j] - m; q = fmaf(d, d, q); }
            float invs = rsqrt_acc(q * (1.0f / DD) + LN_EPS);
            #pragma unroll
            for (int j = 0; j < DD; ++j) {
                int k = t * DD + j;
                xTf[k * 8 + r] = fmaf((v[j] - m) * invs, sm->sb_g1[j], sm->sb_be1[j]);
            }
            // prefetch next step's L / Lm
            if (i < SSEQ - 2) {
                const float* rowp = inp + (size_t)(b0 + r) * SSEQ * FFEAT;
                int tp1 = tp + 1;
                pfL  = rowp[tp1 * FFEAT];
                pfLm = rowp[(tp1 - 1) * FFEAT];
            }
        } else if (tid >= 32 && tid < 32 + RR * 2) {
            int qq = tid - 32;
            int r = qq >> 1, j = qq & 1;
            sm->uS[r][j] = pfU;
            if (i < SSEQ - 2) {
                int ch = 1 + (j ? f1 : f0);
                pfU = inp[(size_t)(b0 + r) * SSEQ * FFEAT + (size_t)(i + 2) * FFEAT + ch];
            }
        }
        __syncthreads();   // S2: xT ready

        // ---- L1: h1 = tanh(x33 @ ew1 + eb1)  K=33, N=512 (full unroll) ----
        {
            const int n = tid;
            u64 a0 = 0, a1 = 0, a2 = 0, a3 = 0;
            const float* wp1 = ew1 + n;
            const ulonglong2* xp = reinterpret_cast<const ulonglong2*>(&sm->xT[0][0]);
            #pragma unroll
            for (int k = 0; k < LBK * DD; ++k) {
                float w = wp1[k * H1N];
                u64 ww = pack2(w, w);
                ulonglong2 x01 = xp[2 * k], x23 = xp[2 * k + 1];
                fma2(a0, x01.x, ww); fma2(a1, x01.y, ww);
                fma2(a2, x23.x, ww); fma2(a3, x23.y, ww);
            }
            float v[8];
            unpack2(a0, v[0], v[1]); unpack2(a1, v[2], v[3]);
            unpack2(a2, v[4], v[5]); unpack2(a3, v[6], v[7]);
            float b = sm->sb_eb1[n];
            float4 o0, o1;
            o0.x = tanh_acc(v[0] + b); o0.y = tanh_acc(v[1] + b);
            o0.z = tanh_acc(v[2] + b); o0.w = tanh_acc(v[3] + b);
            o1.x = tanh_acc(v[4] + b); o1.y = tanh_acc(v[5] + b);
            o1.z = tanh_acc(v[6] + b); o1.w = tanh_acc(v[7] + b);
            sm->h1T[n][0] = o0; sm->h1T[n][1] = o1;
        }
        __syncthreads();   // S3: h1T ready

        // ---- L2 main: h1 @ ew2, K=512 (8 splits), FULL UNROLL 64 iters ----
        // Constant indices let ptxas hoist weight LDGs for deep MLP (no MOV
        // rotation, no single-outstanding-load 234-cyc serialization).
        {
            u64 acc[16];
            #pragma unroll
            for (int j = 0; j < 16; ++j) acc[j] = 0;
            const float4* wp = (const float4*)ew2 + (size_t)(s6 << 6) * 64 + cg6;
            const ulonglong2* xp = reinterpret_cast<const ulonglong2*>(&sm->h1T[s6 << 6][0]);
            #pragma unroll
            for (int kk = 0; kk < 64; ++kk) {
                float4 w = wp[kk * 64];
                ulonglong2 x01 = xp[3 * kk], x23 = xp[3 * kk + 1];
                GBODYI(w, x01, x23);
            }
            ulonglong2* rb = reinterpret_cast<ulonglong2*>(sm->red + ((s6 << 6) + cg6) * 18);
            #pragma unroll
            for (int j = 0; j < 8; ++j) rb[j] = make_ulonglong2(acc[2 * j], acc[2 * j + 1]);
        }
        __syncthreads();   // S4: partials stored

        // ---- L2 reduction (all 512 threads): bias, write hT + hh ----
        {
            #pragma unroll
            for (int rep = 0; rep < 2; ++rep) {
                int o = tid + (rep << 9);
                int cgo = o >> 4, idx = o & 15;
                const u64* rp = sm->red + cgo * 18 + idx;
                u64 a = rp[0];
                #pragma unroll
                for (int sI = 1; sI < 8; ++sI) a = add2(a, rp[sI * 1152]);
                int c = idx >> 2, q = idx & 3;
                int n = (cgo << 2) + c;
                float lo, hi; unpack2(a, lo, hi);
                float b = sm->sb_eb2[n]; lo += b; hi += b;
                hTu[(n << 2) + q] = pack2(lo, hi);
                sm->hh[2 * q][n] = lo; sm->hh[2 * q + 1][n] = hi;
            }
        }
        __syncthreads();   // S5: hT/hh ready, red free

        // ---- L3 main: h @ uw, K=256 (8 splits), FULL UNROLL 32 iters ----
        {
            u64 acc[16];
            #pragma unroll
            for (int j = 0; j < 16; ++j) acc[j] = 0;
            const float4* wp = (const float4*)uw + (size_t)(s6 << 5) * 64 + cg6;
            const ulonglong2* xp = reinterpret_cast<const ulonglong2*>(&sm->hT[s6 << 5][0]);
            #pragma unroll
            for (int kk = 0; kk < 32; ++kk) {
                float4 w = wp[kk * 64];
                ulonglong2 x01 = xp[2 * kk], x23 = xp[2 * kk + 1];
                GBODYI(w, x01, x23);
            }
            ulonglong2* rb = reinterpret_cast<ulonglong2*>(sm->red + ((s6 << 6) + cg6) * 18);
            #pragma unroll
            for (int j = 0; j < 8; ++j) rb[j] = make_ulonglong2(acc[2 * j], acc[2 * j + 1]);
        }
        __syncthreads();   // S6

        // ---- L3 reduction: bias, write ss ----
        {
            #pragma unroll
            for (int rep = 0; rep < 2; ++rep) {
                int o = tid + (rep << 9);
                int cgo = o >> 4, idx = o & 15;
                const u64* rp = sm->red + cgo * 18 + idx;
                u64 a = rp[0];
                #pragma unroll
                for (int sI = 1; sI < 8; ++sI) a = add2(a, rp[sI * 1152]);
                int c = idx >> 2, q = idx & 3;
                int n = (cgo << 2) + c;
                float lo, hi; unpack2(a, lo, hi);
                float b = sm->sb_ub[n]; lo += b; hi += b;
                sm->ss[2 * q][n] = lo; sm->ss[2 * q + 1][n] = hi;
            }
        }
        __syncthreads();   // S7

        // ---- LN2 + ect -> combT (warp w handles row w) ----
        if (tid < 256) {
            int r = tid >> 5, lane = tid & 31;
            float s = 0.f, e = 0.f;
            float vv[8];
            #pragma unroll
            for (int j = 0; j < 8; ++j) {
                int n = lane + (j << 5);
                float v = sm->ss[r][n];
                vv[j] = v;
                s += v;
                e = fmaf(sm->hh[r][n], sm->sb_bw[n], e);
            }
            #pragma unroll
            for (int o = 16; o > 0; o >>= 1) {
                s += __shfl_xor_sync(0xffffffffu, s, o);
                e += __shfl_xor_sync(0xffffffffu, e, o);
            }
            float m = s * (1.0f / UU);
            float q = 0.f;
            #pragma unroll
            for (int j = 0; j < 8; ++j) { float d = vv[j] - m; q = fmaf(d, d, q); }
            #pragma unroll
            for (int o = 16; o > 0; o >>= 1)
                q += __shfl_xor_sync(0xffffffffu, q, o);
            float invs = rsqrt_acc(q * (1.0f / UU) + LN_EPS);
            #pragma unroll
            for (int j = 0; j < 8; ++j) {
                int n = lane + (j << 5);
                combTf[n * 8 + r] = fmaf((vv[j] - m) * invs, sm->sb_g2[n], sm->sb_be2[n]);
            }
            if (lane == 0) combTf[UU * 8 + r] = e;
        }
        __syncthreads();   // S8: combT ready

        // ---- dec1 main: comb[0:256] @ dw1, K=256 (4 splits), FULL UNROLL ----
        {
            u64 acc[16];
            #pragma unroll
            for (int j = 0; j < 16; ++j) acc[j] = 0;
            const float4* wp = (const float4*)dw1 + (size_t)(s7 << 6) * 128 + cg7;
            const ulonglong2* xp = reinterpret_cast<const ulonglong2*>(&sm->combT[s7 << 6][0]);
            #pragma unroll
            for (int kk = 0; kk < 64; ++kk) {
                float4 w = wp[kk * 128];
                ulonglong2 x01 = xp[2 * kk], x23 = xp[2 * kk + 1];
                GBODYI(w, x01, x23);
            }
            ulonglong2* rb = reinterpret_cast<ulonglong2*>(sm->red + ((s7 << 7) + cg7) * 18);
            #pragma unroll
            for (int j = 0; j < 8; ++j) rb[j] = make_ulonglong2(acc[2 * j], acc[2 * j + 1]);
        }
        __syncthreads();   // S9

        // ---- dec1 reduction + ect column + bias + tanh -> gg ----
        {
            #pragma unroll
            for (int rep = 0; rep < 4; ++rep) {
                int o = tid + (rep << 9);
                int cgo = o >> 4, idx = o & 15;
                const u64* rp = sm->red + cgo * 18 + idx;
                u64 a = rp[0];
                #pragma unroll
                for (int sI = 1; sI < 4; ++sI) a = add2(a, rp[sI * 2304]);
                int c = idx >> 2, q = idx & 3;
                int n = (cgo << 2) + c;
                float lo, hi; unpack2(a, lo, hi);
                float b  = sm->sb_db1[n];
                float we = sm->sdw1e[n];
                float elo = combTf[UU * 8 + 2 * q];
                float ehi = combTf[UU * 8 + 2 * q + 1];
                lo = fmaf(elo, we, lo) + b;
                hi = fmaf(ehi, we, hi) + b;
                sm->gg[2 * q][n]     = tanh_acc(lo);
                sm->gg[2 * q + 1][n] = tanh_acc(hi);
            }
        }
        __syncthreads();   // S10: gg ready

        // ---- dec2 partial: gg @ dw2, K=512 split 8, N=8 ----
        {
            int kg  = tid >> 6;
            int idx = tid & 63;
            int n   = idx & 7;
            int r   = idx >> 3;
            float acc = 0.f;
            int kbase = kg << 6;
            #pragma unroll 8
            for (int kk = 0; kk < 64; ++kk) {
                int k = kbase + kk;
                acc = fmaf(sm->gg[r][k], sm->sdw2[k][n], acc);
            }
            sm->redF[tid] = acc;
        }
        __syncthreads();   // S11

        // ---- dec2 final + output (warps 0,1); loop-top bar#1 orders with phase0
        if (tid < 64) {
            int n = tid & 7, r = tid >> 3;
            float y = sm->sb_db2[n];
            #pragma unroll
            for (int j = 0; j < 8; ++j) y += sm->redF[(j << 6) + tid];
            if (n == f0) y = sm->uS[r][0];
            if (n == f1) y = sm->uS[r][1];
            sm->yS[r][n] = y;
            out[(size_t)n * BB * TOUTN + (size_t)(b0 + r) * TOUTN + (i - LBK)] = y;
        }
    }
}

extern "C" void kernel_launch(void* const* d_in, const int* in_sizes, int n_in,
                              void* d_out, int out_size) {
    const float* inp = (const float*)d_in[0];
    const float* g1  = (const float*)d_in[1];
    const float* be1 = (const float*)d_in[2];
    const float* ew1 = (const float*)d_in[3];
    const float* eb1 = (const float*)d_in[4];
    const float* ew2 = (const float*)d_in[5];
    const float* eb2 = (const float*)d_in[6];
    const float* uw  = (const float*)d_in[7];
    const float* ub  = (const float*)d_in[8];
    const float* g2  = (const float*)d_in[9];
    const float* be2 = (const float*)d_in[10];
    const float* bw  = (const float*)d_in[11];
    const float* dw1 = (const float*)d_in[12];
    const float* db1 = (const float*)d_in[13];
    const float* dw2 = (const float*)d_in[14];
    const float* db2 = (const float*)d_in[15];
    const int*  fixp = (const int*)d_in[16];
    float* out = (float*)d_out;

    cudaFuncSetAttribute(dps_kernel, cudaFuncAttributeMaxDynamicSharedMemorySize,
                         (int)sizeof(SmemT));
    dps_kernel<<<NBLK, NT, sizeof(SmemT)>>>(inp, g1, be1, ew1, eb1, ew2, eb2,
                                            uw, ub, g2, be2, bw, dw1, db1,
                                            dw2, db2, fixp, out);
}